// round 12
// baseline (speedup 1.0000x reference)
#include <cuda_runtime.h>
#include <cuda_bf16.h>
#include <math.h>
#include <stdint.h>

#define S_LEN 1024
#define D_MODEL 1024
#define NH 16
#define DH 64
#define L_LAYERS 4
#define DFF 4096
#define TPF 8
#define NFRAMES (S_LEN / TPF)
#define QBLK 4
#define QROWS (QBLK * TPF)

// ---------------- scratch (device globals; no allocation) ----------------
__device__ float g_qkv[S_LEN * 3 * D_MODEL];
__device__ float g_mod[L_LAYERS * 6 * D_MODEL];
__device__ float g_ropec[S_LEN * 32];
__device__ float g_ropes[S_LEN * 32];
__device__ __nv_bfloat16 g_abuf[1024 * 2048];
__device__ __nv_bfloat16 g_abuf2[1024 * 8192];
// per-weight split buffers, all layers: [L][2K, N] (hi rows | lo rows)
__device__ __nv_bfloat16 g_wqkv[L_LAYERS * 2048 * 3072];
__device__ __nv_bfloat16 g_wout[L_LAYERS * 2048 * 1024];
__device__ __nv_bfloat16 g_w1[L_LAYERS * 2048 * 4096];
__device__ __nv_bfloat16 g_w2[L_LAYERS * 8192 * 1024];

// ---------------- helpers ----------------
__device__ __forceinline__ uint32_t smem_u32(const void* p) {
    uint32_t a;
    asm("{ .reg .u64 t; cvta.to.shared.u64 t, %1; cvt.u32.u64 %0, t; }" : "=r"(a) : "l"(p));
    return a;
}
#define CP16(dst, src) \
    asm volatile("cp.async.cg.shared.global [%0], [%1], 16;" :: "r"(dst), "l"(src))
#define CP_COMMIT() asm volatile("cp.async.commit_group;")
#define CP_WAIT(n)  asm volatile("cp.async.wait_group %0;" :: "n"(n))
#define LDSM4(r0, r1, r2, r3, addr)                                        \
    asm volatile("ldmatrix.sync.aligned.m8n8.x4.shared.b16 {%0,%1,%2,%3}, [%4];" \
        : "=r"(r0), "=r"(r1), "=r"(r2), "=r"(r3) : "r"(addr))
#define LDSM4T(r0, r1, r2, r3, addr)                                       \
    asm volatile("ldmatrix.sync.aligned.m8n8.x4.trans.shared.b16 {%0,%1,%2,%3}, [%4];" \
        : "=r"(r0), "=r"(r1), "=r"(r2), "=r"(r3) : "r"(addr))
#define MMA(acc, ar, br)                                                   \
    asm volatile(                                                          \
        "mma.sync.aligned.m16n8k16.row.col.f32.bf16.bf16.f32 "             \
        "{%0,%1,%2,%3}, {%4,%5,%6,%7}, {%8,%9}, {%0,%1,%2,%3};"            \
        : "+f"((acc)[0]), "+f"((acc)[1]), "+f"((acc)[2]), "+f"((acc)[3])   \
        : "r"((ar)[0]), "r"((ar)[1]), "r"((ar)[2]), "r"((ar)[3]),          \
          "r"((br)[0]), "r"((br)[1]))

__device__ __forceinline__ float gelu_tanh(float v) {
    float t = tanhf(0.7978845608028654f * (v + 0.044715f * v * v * v));
    return 0.5f * v * (1.f + t);
}

__device__ __forceinline__ void store_split2(__nv_bfloat16* Cs, size_t rowbase, int col,
                                             int N, float a, float b) {
    __nv_bfloat162 hi, lo;
    hi.x = __float2bfloat16(a);
    hi.y = __float2bfloat16(b);
    lo.x = __float2bfloat16(a - __bfloat162float(hi.x));
    lo.y = __float2bfloat16(b - __bfloat162float(hi.y));
    *(__nv_bfloat162*)(Cs + rowbase + col)     = hi;
    *(__nv_bfloat162*)(Cs + rowbase + N + col) = lo;
}

// ---------------- batched weight split: W [L][K,N] fp32 -> [L][2K,N] bf16 ----------------
__global__ void split_w_all(const float* __restrict__ W, __nv_bfloat16* __restrict__ out,
                            int K, int N) {
    int n0 = blockIdx.x * 1024 + threadIdx.x * 4;
    int k = blockIdx.y;
    int layer = blockIdx.z;
    const float* Wl = W + (size_t)layer * K * N;
    __nv_bfloat16* ol = out + (size_t)layer * 2 * K * N;
    float4 w = *(const float4*)(Wl + (size_t)k * N + n0);
    __nv_bfloat162 h0, h1, l0, l1;
    h0.x = __float2bfloat16(w.x); h0.y = __float2bfloat16(w.y);
    h1.x = __float2bfloat16(w.z); h1.y = __float2bfloat16(w.w);
    l0.x = __float2bfloat16(w.x - __bfloat162float(h0.x));
    l0.y = __float2bfloat16(w.y - __bfloat162float(h0.y));
    l1.x = __float2bfloat16(w.z - __bfloat162float(h1.x));
    l1.y = __float2bfloat16(w.w - __bfloat162float(h1.y));
    uint2 hu, lu;
    hu.x = *(uint32_t*)&h0; hu.y = *(uint32_t*)&h1;
    lu.x = *(uint32_t*)&l0; lu.y = *(uint32_t*)&l1;
    *(uint2*)(ol + (size_t)k * N + n0)       = hu;
    *(uint2*)(ol + (size_t)(K + k) * N + n0) = lu;
}

// ---------------- mma.sync bf16 3-term GEMM, 3-stage pipeline, 1 sync/chunk ----------------
template <int MODE, int BM>
__global__ void __launch_bounds__(256, 2)
mma_gemm(const __nv_bfloat16* __restrict__ A, const __nv_bfloat16* __restrict__ B,
         const float* __restrict__ bias, const float* __restrict__ gate,
         float* __restrict__ C, __nv_bfloat16* __restrict__ Cs,
         const float* __restrict__ X, int M, int N, int K) {
    constexpr int WARPS_M = BM / 32;
    constexpr int WARPS_N = 8 / WARPS_M;
    constexpr int WTN = 128 / WARPS_N;
    constexpr int NAT = WTN / 8;
    constexpr int ROWA = 80;
    constexpr int ROWB = 272;
    constexpr int OFF_AL = BM * ROWA;
    constexpr int OFF_BH = 2 * BM * ROWA;
    constexpr int STG = 2 * BM * ROWA + 2 * 32 * ROWB;
    constexpr int A_OPS = BM / 64;
    constexpr int B_OPS = 2;

    extern __shared__ __align__(128) char dyn[];
    uint32_t sb = smem_u32(dyn);
    int tid = threadIdx.x;
    int wid = tid >> 5, lane = tid & 31;
    int wm = wid / WARPS_N, wn = wid % WARPS_N;
    int bm = blockIdx.y * BM, bn = blockIdx.x * 128;

    float acc[2][NAT][4];
    #pragma unroll
    for (int i = 0; i < 2; i++)
        #pragma unroll
        for (int j = 0; j < NAT; j++)
            #pragma unroll
            for (int q = 0; q < 4; q++) acc[i][j][q] = 0.f;

    int nch = K >> 5;

    const __nv_bfloat16* srcA[A_OPS];
    uint32_t dA[A_OPS];
    #pragma unroll
    for (int i = 0; i < A_OPS; i++) {
        int idx = tid + i * 256;
        int r = idx >> 2, seg = idx & 3;
        srcA[i] = A + (size_t)(bm + r) * (2 * K) + seg * 8;
        dA[i] = sb + r * ROWA + seg * 16;
    }
    const __nv_bfloat16* srcB[B_OPS];
    uint32_t dB[B_OPS];
    #pragma unroll
    for (int i = 0; i < B_OPS; i++) {
        int idx = tid + i * 256;
        int r = idx >> 4, seg = idx & 15;
        srcB[i] = B + (size_t)r * N + bn + seg * 8;
        dB[i] = sb + OFF_BH + r * ROWB + seg * 16;
    }

    auto issue = [&](int kc, int st) {
        uint32_t so = st * STG;
        #pragma unroll
        for (int i = 0; i < A_OPS; i++) {
            CP16(dA[i] + so, srcA[i] + kc * 32);
            CP16(dA[i] + so + OFF_AL, srcA[i] + K + kc * 32);
        }
        #pragma unroll
        for (int i = 0; i < B_OPS; i++) {
            CP16(dB[i] + so, srcB[i] + (size_t)kc * 32 * N);
            CP16(dB[i] + so + 32 * ROWB, srcB[i] + (size_t)(K + kc * 32) * N);
        }
    };

    issue(0, 0); CP_COMMIT();
    issue(1, 1); CP_COMMIT();

    int grp = lane >> 3, lr = lane & 7;
    uint32_t aoff[2][2];
    #pragma unroll
    for (int ks = 0; ks < 2; ks++)
        #pragma unroll
        for (int ma = 0; ma < 2; ma++)
            aoff[ks][ma] = (wm * 32 + ma * 16 + (grp & 1) * 8 + lr) * ROWA +
                           (ks * 16 + (grp >> 1) * 8) * 2;
    uint32_t boff[2][NAT / 2];
    #pragma unroll
    for (int ks = 0; ks < 2; ks++)
        #pragma unroll
        for (int p = 0; p < NAT / 2; p++)
            boff[ks][p] = OFF_BH + (ks * 16 + lr + (grp & 1) * 8) * ROWB +
                          (wn * WTN + p * 16 + ((lane >> 4) & 1) * 8) * 2;

    int st_c = 0, st_n = 2;
    for (int c = 0; c < nch; c++) {
        CP_WAIT(1);
        __syncthreads();
        if (c + 2 < nch) issue(c + 2, st_n);
        CP_COMMIT();

        uint32_t base = sb + st_c * STG;
        st_c = (st_c == 2) ? 0 : st_c + 1;
        st_n = (st_n == 2) ? 0 : st_n + 1;

        #pragma unroll
        for (int ks = 0; ks < 2; ks++) {
            uint32_t ah[2][4], al[2][4];
            #pragma unroll
            for (int ma = 0; ma < 2; ma++) {
                LDSM4(ah[ma][0], ah[ma][1], ah[ma][2], ah[ma][3], base + aoff[ks][ma]);
                LDSM4(al[ma][0], al[ma][1], al[ma][2], al[ma][3],
                      base + aoff[ks][ma] + OFF_AL);
            }
            #pragma unroll
            for (int p = 0; p < NAT / 2; p++) {
                uint32_t b0[2], b1[2];
                LDSM4T(b0[0], b0[1], b1[0], b1[1], base + boff[ks][p]);
                #pragma unroll
                for (int ma = 0; ma < 2; ma++) {
                    MMA(acc[ma][2 * p],     ah[ma], b0);
                    MMA(acc[ma][2 * p + 1], ah[ma], b1);
                    MMA(acc[ma][2 * p],     al[ma], b0);
                    MMA(acc[ma][2 * p + 1], al[ma], b1);
                }
            }
            #pragma unroll
            for (int p = 0; p < NAT / 2; p++) {
                uint32_t b0[2], b1[2];
                LDSM4T(b0[0], b0[1], b1[0], b1[1], base + boff[ks][p] + 32 * ROWB);
                #pragma unroll
                for (int ma = 0; ma < 2; ma++) {
                    MMA(acc[ma][2 * p],     ah[ma], b0);
                    MMA(acc[ma][2 * p + 1], ah[ma], b1);
                }
            }
        }
    }

    int tr = lane >> 2, tc = (lane & 3) * 2;
    #pragma unroll
    for (int ma = 0; ma < 2; ma++) {
        int row = bm + wm * 32 + ma * 16 + tr;
        #pragma unroll
        for (int na = 0; na < NAT; na++) {
            int col = bn + wn * WTN + na * 8 + tc;
            float2 bv = *(const float2*)(bias + col);
            float v0 = acc[ma][na][0] + bv.x;
            float v1 = acc[ma][na][1] + bv.y;
            float v2 = acc[ma][na][2] + bv.x;
            float v3 = acc[ma][na][3] + bv.y;
            if (MODE == 1) {
                v0 = gelu_tanh(v0); v1 = gelu_tanh(v1);
                v2 = gelu_tanh(v2); v3 = gelu_tanh(v3);
                store_split2(Cs, (size_t)row * 2 * N, col, N, v0, v1);
                store_split2(Cs, (size_t)(row + 8) * 2 * N, col, N, v2, v3);
            } else {
                if (MODE == 2) {
                    float2 gv = *(const float2*)(gate + col);
                    float2 x0 = *(const float2*)(X + (size_t)row * N + col);
                    float2 x1 = *(const float2*)(X + (size_t)(row + 8) * N + col);
                    v0 = x0.x + v0 * gv.x; v1 = x0.y + v1 * gv.y;
                    v2 = x1.x + v2 * gv.x; v3 = x1.y + v3 * gv.y;
                }
                *(float2*)(C + (size_t)row * N + col)       = make_float2(v0, v1);
                *(float2*)(C + (size_t)(row + 8) * N + col) = make_float2(v2, v3);
            }
        }
    }
}

// ---------------- mod/gate precompute ----------------
__global__ void modgate_kernel(const float* __restrict__ cond,
                               const float* __restrict__ a1w, const float* __restrict__ a1b,
                               const float* __restrict__ g1w, const float* __restrict__ g1b,
                               const float* __restrict__ a2w, const float* __restrict__ a2b,
                               const float* __restrict__ g2w, const float* __restrict__ g2b,
                               float* __restrict__ out) {
    __shared__ float cs[D_MODEL];
    for (int i = threadIdx.x; i < D_MODEL; i += blockDim.x) cs[i] = cond[i];
    __syncthreads();
    int o = blockIdx.x * blockDim.x + threadIdx.x;
    int l = o / (6 * D_MODEL);
    int j = o % (6 * D_MODEL);
    const float* W; const float* Bv; int col, ncols;
    if (j < 2 * D_MODEL)      { W = a1w + (size_t)l * D_MODEL * 2 * D_MODEL; Bv = a1b + l * 2 * D_MODEL; col = j;               ncols = 2 * D_MODEL; }
    else if (j < 3 * D_MODEL) { W = g1w + (size_t)l * D_MODEL * D_MODEL;     Bv = g1b + l * D_MODEL;     col = j - 2 * D_MODEL; ncols = D_MODEL; }
    else if (j < 5 * D_MODEL) { W = a2w + (size_t)l * D_MODEL * 2 * D_MODEL; Bv = a2b + l * 2 * D_MODEL; col = j - 3 * D_MODEL; ncols = 2 * D_MODEL; }
    else                      { W = g2w + (size_t)l * D_MODEL * D_MODEL;     Bv = g2b + l * D_MODEL;     col = j - 5 * D_MODEL; ncols = D_MODEL; }
    float acc = 0.f;
    #pragma unroll 8
    for (int d = 0; d < D_MODEL; d++) acc += cs[d] * W[(size_t)d * ncols + col];
    out[o] = acc + Bv[col];
}

// ---------------- LayerNorm + adaLN modulation, fused bf16 split out ----------------
__global__ void ln_mod_kernel(const float* __restrict__ x,
                              const float* __restrict__ shift,
                              const float* __restrict__ scale,
                              __nv_bfloat16* __restrict__ out) {
    int row = blockIdx.x;
    int tid = threadIdx.x;
    const float* xr = x + (size_t)row * D_MODEL;
    float v[4], s = 0.f, s2 = 0.f;
    #pragma unroll
    for (int i = 0; i < 4; i++) {
        v[i] = xr[tid + i * 256];
        s += v[i]; s2 += v[i] * v[i];
    }
    #pragma unroll
    for (int off = 16; off; off >>= 1) {
        s  += __shfl_xor_sync(0xffffffff, s,  off);
        s2 += __shfl_xor_sync(0xffffffff, s2, off);
    }
    __shared__ float sh1[8], sh2[8];
    int w = tid >> 5, lane = tid & 31;
    if (lane == 0) { sh1[w] = s; sh2[w] = s2; }
    __syncthreads();
    if (tid == 0) {
        float a = 0.f, b = 0.f;
        #pragma unroll
        for (int i = 0; i < 8; i++) { a += sh1[i]; b += sh2[i]; }
        sh1[0] = a; sh2[0] = b;
    }
    __syncthreads();
    float mean = sh1[0] * (1.f / D_MODEL);
    float var  = sh2[0] * (1.f / D_MODEL) - mean * mean;
    float r = rsqrtf(var + 1e-5f);
    __nv_bfloat16* orow = out + (size_t)row * 2 * D_MODEL;
    #pragma unroll
    for (int i = 0; i < 4; i++) {
        int col = tid + i * 256;
        float hv = (v[i] - mean) * r * (1.f + scale[col]) + shift[col];
        __nv_bfloat16 hi = __float2bfloat16(hv);
        orow[col]           = hi;
        orow[D_MODEL + col] = __float2bfloat16(hv - __bfloat162float(hi));
    }
}

// ---------------- RoPE table (fp64 once) ----------------
__global__ void rope_table_kernel(float* __restrict__ rc, float* __restrict__ rs) {
    int idx = blockIdx.x * 256 + threadIdx.x;
    int s = idx >> 5, j = idx & 31;
    double inv = exp(-((double)j / 32.0) * 9.210340371976184);
    double ang = (double)s * inv;
    rc[idx] = (float)cos(ang);
    rs[idx] = (float)sin(ang);
}

// ---------------- per-(token,head) RMSNorm + RoPE ----------------
__global__ void rmsrope_kernel(float* __restrict__ qkv,
                               const float* __restrict__ rc,
                               const float* __restrict__ rs) {
    int s = blockIdx.x;
    int warp = threadIdx.x >> 5, lane = threadIdx.x & 31;
    int hh = blockIdx.y * 8 + warp;
    int which = hh >> 4;
    int h = hh & 15;
    float* base = qkv + (size_t)s * 3 * D_MODEL + which * D_MODEL + h * DH;
    float x1 = base[lane], x2 = base[lane + 32];
    float ss = x1 * x1 + x2 * x2;
    #pragma unroll
    for (int off = 16; off; off >>= 1) ss += __shfl_xor_sync(0xffffffff, ss, off);
    float r = rsqrtf(ss * (1.f / DH) + 1e-6f);
    x1 *= r; x2 *= r;
    float c = rc[s * 32 + lane], sn = rs[s * 32 + lane];
    base[lane]      = x1 * c - x2 * sn;
    base[lane + 32] = x1 * sn + x2 * c;
}

// ---------------- frame-masked flash attention, 4 frames/block ----------------
__global__ void __launch_bounds__(256, 4)
attn_kernel(const float* __restrict__ qkv, __nv_bfloat16* __restrict__ Oa, int window) {
    int F0 = blockIdx.x * QBLK;
    int h = blockIdx.y;
    int tid = threadIdx.x;
    int warp = tid >> 5, lane = tid & 31;
    __shared__ float Qs[QROWS][DH];
    __shared__ float Ks[32][DH + 4];
    __shared__ float Vs[32][DH + 2];
    int h0 = h * DH;
    int qrow0 = F0 * TPF;
    for (int i = tid; i < QROWS * DH; i += 256) {
        int r = i >> 6, d = i & 63;
        Qs[r][d] = qkv[(size_t)(qrow0 + r) * 3 * D_MODEL + h0 + d];
    }
    __syncthreads();

    int kstart = max(0, F0 - window + 1) * TPF;
    int kend = (F0 + QBLK) * TPF;
    int nk = kend - kstart;

    float m[QBLK], l[QBLK], o0[QBLK], o1[QBLK];
    #pragma unroll
    for (int qi = 0; qi < QBLK; qi++) { m[qi] = -1e30f; l[qi] = 0.f; o0[qi] = 0.f; o1[qi] = 0.f; }
    int d0 = lane * 2;
    const float sc = 0.125f;

    for (int c0 = 0; c0 < nk; c0 += 32) {
        for (int i = tid; i < 32 * DH; i += 256) {
            int r = i >> 6, d = i & 63;
            int kr = kstart + c0 + r;
            if (kr > S_LEN - 1) kr = S_LEN - 1;
            Ks[r][d] = qkv[(size_t)kr * 3 * D_MODEL + D_MODEL + h0 + d];
            Vs[r][d] = qkv[(size_t)kr * 3 * D_MODEL + 2 * D_MODEL + h0 + d];
        }
        __syncthreads();

        int kr = kstart + c0 + lane;
        int fk = kr >> 3;
        bool inrange = (c0 + lane < nk);

        #pragma unroll
        for (int qi = 0; qi < QBLK; qi++) {
            int q = warp + 8 * qi;
            int fq = F0 + qi;
            bool valid = inrange && (fk <= fq) && (fq - fk < window);
            float s;
            {
                float a0 = 0.f, a1 = 0.f, a2 = 0.f, a3 = 0.f;
                #pragma unroll
                for (int d = 0; d < DH; d += 4) {
                    a0 = fmaf(Qs[q][d],     Ks[lane][d],     a0);
                    a1 = fmaf(Qs[q][d + 1], Ks[lane][d + 1], a1);
                    a2 = fmaf(Qs[q][d + 2], Ks[lane][d + 2], a2);
                    a3 = fmaf(Qs[q][d + 3], Ks[lane][d + 3], a3);
                }
                s = valid ? (a0 + a1 + a2 + a3) * sc : -1e30f;
            }
            float cm = s;
            #pragma unroll
            for (int off = 16; off; off >>= 1)
                cm = fmaxf(cm, __shfl_xor_sync(0xffffffff, cm, off));
            float mnew = fmaxf(m[qi], cm);
            float p = valid ? __expf(s - mnew) : 0.f;
            float ps = p;
            #pragma unroll
            for (int off = 16; off; off >>= 1)
                ps += __shfl_xor_sync(0xffffffff, ps, off);
            float factor = __expf(m[qi] - mnew);
            l[qi] = l[qi] * factor + ps;
            m[qi] = mnew;
            o0[qi] *= factor; o1[qi] *= factor;
            #pragma unroll
            for (int k = 0; k < 32; k++) {
                float pk = __shfl_sync(0xffffffff, p, k);
                o0[qi] = fmaf(pk, Vs[k][d0],     o0[qi]);
                o1[qi] = fmaf(pk, Vs[k][d0 + 1], o1[qi]);
            }
        }
        __syncthreads();
    }

    #pragma unroll
    for (int qi = 0; qi < QBLK; qi++) {
        float invl = 1.f / l[qi];
        float a = o0[qi] * invl, b = o1[qi] * invl;
        __nv_bfloat162 hi, lo;
        hi.x = __float2bfloat16(a);
        hi.y = __float2bfloat16(b);
        lo.x = __float2bfloat16(a - __bfloat162float(hi.x));
        lo.y = __float2bfloat16(b - __bfloat162float(hi.y));
        size_t rb = (size_t)(qrow0 + warp + 8 * qi) * 2 * D_MODEL;
        *(__nv_bfloat162*)(Oa + rb + h0 + d0)           = hi;
        *(__nv_bfloat162*)(Oa + rb + D_MODEL + h0 + d0) = lo;
    }
}

// ---------------- host-side orchestration ----------------
extern "C" void kernel_launch(void* const* d_in, const int* in_sizes, int n_in,
                              void* d_out, int out_size) {
    const float* x       = (const float*)d_in[0];
    const float* cond    = (const float*)d_in[1];
    const float* qkv_w   = (const float*)d_in[2];
    const float* qkv_b   = (const float*)d_in[3];
    const float* out_w   = (const float*)d_in[4];
    const float* out_b   = (const float*)d_in[5];
    const float* mlp_w1  = (const float*)d_in[6];
    const float* mlp_b1  = (const float*)d_in[7];
    const float* mlp_w2  = (const float*)d_in[8];
    const float* mlp_b2  = (const float*)d_in[9];
    const float* ada1_w  = (const float*)d_in[10];
    const float* ada1_b  = (const float*)d_in[11];
    const float* gate1_w = (const float*)d_in[12];
    const float* gate1_b = (const float*)d_in[13];
    const float* ada2_w  = (const float*)d_in[14];
    const float* ada2_b  = (const float*)d_in[15];
    const float* gate2_w = (const float*)d_in[16];
    const float* gate2_b = (const float*)d_in[17];
    float* X = (float*)d_out;

    float *qkv_ptr, *mod_ptr, *rc_ptr, *rs_ptr;
    __nv_bfloat16 *abuf, *abuf2, *wqkv, *wout, *w1, *w2;
    cudaGetSymbolAddress((void**)&qkv_ptr, g_qkv);
    cudaGetSymbolAddress((void**)&mod_ptr, g_mod);
    cudaGetSymbolAddress((void**)&rc_ptr,  g_ropec);
    cudaGetSymbolAddress((void**)&rs_ptr,  g_ropes);
    cudaGetSymbolAddress((void**)&abuf,    g_abuf);
    cudaGetSymbolAddress((void**)&abuf2,   g_abuf2);
    cudaGetSymbolAddress((void**)&wqkv,    g_wqkv);
    cudaGetSymbolAddress((void**)&wout,    g_wout);
    cudaGetSymbolAddress((void**)&w1,      g_w1);
    cudaGetSymbolAddress((void**)&w2,      g_w2);

    const int SM128 = (2 * 128 * 80 + 2 * 32 * 272) * 3;  // 113664
    const int SM64  = (2 * 64 * 80 + 2 * 32 * 272) * 3;   // 82944
    cudaFuncSetAttribute(mma_gemm<0, 64>,  cudaFuncAttributeMaxDynamicSharedMemorySize, SM64);
    cudaFuncSetAttribute(mma_gemm<1, 128>, cudaFuncAttributeMaxDynamicSharedMemorySize, SM128);
    cudaFuncSetAttribute(mma_gemm<2, 64>,  cudaFuncAttributeMaxDynamicSharedMemorySize, SM64);

    cudaMemcpyAsync(X, x, (size_t)S_LEN * D_MODEL * sizeof(float), cudaMemcpyDeviceToDevice);

    rope_table_kernel<<<S_LEN * 32 / 256, 256>>>(rc_ptr, rs_ptr);

    modgate_kernel<<<L_LAYERS * 6 * D_MODEL / 256, 256>>>(
        cond, ada1_w, ada1_b, gate1_w, gate1_b, ada2_w, ada2_b, gate2_w, gate2_b, mod_ptr);

    // all weight splits up front (batched over layers)
    split_w_all<<<dim3(3, D_MODEL, L_LAYERS), 256>>>(qkv_w,  wqkv, D_MODEL, 3 * D_MODEL);
    split_w_all<<<dim3(1, D_MODEL, L_LAYERS), 256>>>(out_w,  wout, D_MODEL, D_MODEL);
    split_w_all<<<dim3(4, D_MODEL, L_LAYERS), 256>>>(mlp_w1, w1,   D_MODEL, DFF);
    split_w_all<<<dim3(1, DFF,     L_LAYERS), 256>>>(mlp_w2, w2,   DFF,     D_MODEL);

    for (int i = 0; i < L_LAYERS; i++) {
        const float* mod = mod_ptr + i * 6 * D_MODEL;
        int window = (i % 4 == 0) ? 128 : 8;

        // ---- attention block ----
        ln_mod_kernel<<<S_LEN, 256>>>(X, mod, mod + D_MODEL, abuf);

        mma_gemm<0, 64><<<dim3(3 * D_MODEL / 128, S_LEN / 64), 256, SM64>>>(
            abuf, wqkv + (size_t)i * 2048 * 3072, qkv_b + i * 3 * D_MODEL,
            nullptr, qkv_ptr, nullptr, nullptr, S_LEN, 3 * D_MODEL, D_MODEL);

        rmsrope_kernel<<<dim3(S_LEN, 4), 256>>>(qkv_ptr, rc_ptr, rs_ptr);
        attn_kernel<<<dim3(NFRAMES / QBLK, NH), 256>>>(qkv_ptr, abuf, window);

        mma_gemm<2, 64><<<dim3(D_MODEL / 128, S_LEN / 64), 256, SM64>>>(
            abuf, wout + (size_t)i * 2048 * 1024, out_b + i * D_MODEL,
            mod + 2 * D_MODEL, X, nullptr, X, S_LEN, D_MODEL, D_MODEL);

        // ---- MLP block ----
        ln_mod_kernel<<<S_LEN, 256>>>(X, mod + 3 * D_MODEL, mod + 4 * D_MODEL, abuf);

        mma_gemm<1, 128><<<dim3(DFF / 128, S_LEN / 128), 256, SM128>>>(
            abuf, w1 + (size_t)i * 2048 * 4096, mlp_b1 + i * DFF,
            nullptr, nullptr, abuf2, nullptr, S_LEN, DFF, D_MODEL);

        mma_gemm<2, 64><<<dim3(D_MODEL / 128, S_LEN / 64), 256, SM64>>>(
            abuf2, w2 + (size_t)i * 8192 * 1024, mlp_b2 + i * D_MODEL,
            mod + 5 * D_MODEL, X, nullptr, X, S_LEN, D_MODEL, DFF);
    }
}

// round 15
// speedup vs baseline: 1.0562x; 1.0562x over previous
#include <cuda_runtime.h>
#include <cuda_bf16.h>
#include <math.h>
#include <stdint.h>

#define S_LEN 1024
#define D_MODEL 1024
#define NH 16
#define DH 64
#define L_LAYERS 4
#define DFF 4096
#define TPF 8
#define NFRAMES (S_LEN / TPF)
#define QBLK 4
#define QROWS (QBLK * TPF)

// ---------------- scratch (device globals; no allocation) ----------------
__device__ float g_qkv[S_LEN * 3 * D_MODEL];
__device__ float g_mod[L_LAYERS * 6 * D_MODEL];
__device__ float g_ropec[S_LEN * 32];
__device__ float g_ropes[S_LEN * 32];
__device__ __nv_bfloat16 g_abuf[1024 * 2048];
__device__ __nv_bfloat16 g_abuf2[1024 * 8192];
__device__ __nv_bfloat16 g_wbuf[8192 * 1024];

// ---------------- helpers ----------------
__device__ __forceinline__ uint32_t smem_u32(const void* p) {
    uint32_t a;
    asm("{ .reg .u64 t; cvta.to.shared.u64 t, %1; cvt.u32.u64 %0, t; }" : "=r"(a) : "l"(p));
    return a;
}
#define CP16(dst, src) \
    asm volatile("cp.async.cg.shared.global [%0], [%1], 16;" :: "r"(dst), "l"(src))
#define CP_COMMIT() asm volatile("cp.async.commit_group;")
#define CP_WAIT(n)  asm volatile("cp.async.wait_group %0;" :: "n"(n))
#define LDSM4(r0, r1, r2, r3, addr)                                        \
    asm volatile("ldmatrix.sync.aligned.m8n8.x4.shared.b16 {%0,%1,%2,%3}, [%4];" \
        : "=r"(r0), "=r"(r1), "=r"(r2), "=r"(r3) : "r"(addr))
#define LDSM4T(r0, r1, r2, r3, addr)                                       \
    asm volatile("ldmatrix.sync.aligned.m8n8.x4.trans.shared.b16 {%0,%1,%2,%3}, [%4];" \
        : "=r"(r0), "=r"(r1), "=r"(r2), "=r"(r3) : "r"(addr))
#define MMA(acc, ar, br)                                                   \
    asm volatile(                                                          \
        "mma.sync.aligned.m16n8k16.row.col.f32.bf16.bf16.f32 "             \
        "{%0,%1,%2,%3}, {%4,%5,%6,%7}, {%8,%9}, {%0,%1,%2,%3};"            \
        : "+f"((acc)[0]), "+f"((acc)[1]), "+f"((acc)[2]), "+f"((acc)[3])   \
        : "r"((ar)[0]), "r"((ar)[1]), "r"((ar)[2]), "r"((ar)[3]),          \
          "r"((br)[0]), "r"((br)[1]))

__device__ __forceinline__ float gelu_tanh(float v) {
    float t = tanhf(0.7978845608028654f * (v + 0.044715f * v * v * v));
    return 0.5f * v * (1.f + t);
}

__device__ __forceinline__ void store_split2(__nv_bfloat16* Cs, size_t rowbase, int col,
                                             int N, float a, float b) {
    __nv_bfloat162 hi, lo;
    hi.x = __float2bfloat16(a);
    hi.y = __float2bfloat16(b);
    lo.x = __float2bfloat16(a - __bfloat162float(hi.x));
    lo.y = __float2bfloat16(b - __bfloat162float(hi.y));
    *(__nv_bfloat162*)(Cs + rowbase + col)     = hi;
    *(__nv_bfloat162*)(Cs + rowbase + N + col) = lo;
}

// ---------------- weight split: W [K,N] fp32 -> [2K,N] bf16 (hi rows | lo rows) ----------------
__global__ void split_w_kernel(const float* __restrict__ W, __nv_bfloat16* __restrict__ out,
                               int K, int N) {
    int n0 = blockIdx.x * 1024 + threadIdx.x * 4;
    int k = blockIdx.y;
    float4 w = *(const float4*)(W + (size_t)k * N + n0);
    __nv_bfloat162 h0, h1, l0, l1;
    h0.x = __float2bfloat16(w.x); h0.y = __float2bfloat16(w.y);
    h1.x = __float2bfloat16(w.z); h1.y = __float2bfloat16(w.w);
    l0.x = __float2bfloat16(w.x - __bfloat162float(h0.x));
    l0.y = __float2bfloat16(w.y - __bfloat162float(h0.y));
    l1.x = __float2bfloat16(w.z - __bfloat162float(h1.x));
    l1.y = __float2bfloat16(w.w - __bfloat162float(h1.y));
    uint2 hu, lu;
    hu.x = *(uint32_t*)&h0; hu.y = *(uint32_t*)&h1;
    lu.x = *(uint32_t*)&l0; lu.y = *(uint32_t*)&l1;
    *(uint2*)(out + (size_t)k * N + n0)       = hu;
    *(uint2*)(out + (size_t)(K + k) * N + n0) = lu;
}

// ---------------- mma.sync bf16 3-term GEMM, 3-stage pipeline, 1 sync/chunk ----------------
template <int MODE, int BM>
__global__ void __launch_bounds__(256, 2)
mma_gemm(const __nv_bfloat16* __restrict__ A, const __nv_bfloat16* __restrict__ B,
         const float* __restrict__ bias, const float* __restrict__ gate,
         float* __restrict__ C, __nv_bfloat16* __restrict__ Cs,
         const float* __restrict__ X, int M, int N, int K) {
    constexpr int WARPS_M = BM / 32;
    constexpr int WARPS_N = 8 / WARPS_M;
    constexpr int WTN = 128 / WARPS_N;
    constexpr int NAT = WTN / 8;
    constexpr int ROWA = 80;
    constexpr int ROWB = 272;
    constexpr int OFF_AL = BM * ROWA;
    constexpr int OFF_BH = 2 * BM * ROWA;
    constexpr int STG = 2 * BM * ROWA + 2 * 32 * ROWB;
    constexpr int A_OPS = BM / 64;
    constexpr int B_OPS = 2;

    extern __shared__ __align__(128) char dyn[];
    uint32_t sb = smem_u32(dyn);
    int tid = threadIdx.x;
    int wid = tid >> 5, lane = tid & 31;
    int wm = wid / WARPS_N, wn = wid % WARPS_N;
    int bm = blockIdx.y * BM, bn = blockIdx.x * 128;

    float acc[2][NAT][4];
    #pragma unroll
    for (int i = 0; i < 2; i++)
        #pragma unroll
        for (int j = 0; j < NAT; j++)
            #pragma unroll
            for (int q = 0; q < 4; q++) acc[i][j][q] = 0.f;

    int nch = K >> 5;

    const __nv_bfloat16* srcA[A_OPS];
    uint32_t dA[A_OPS];
    #pragma unroll
    for (int i = 0; i < A_OPS; i++) {
        int idx = tid + i * 256;
        int r = idx >> 2, seg = idx & 3;
        srcA[i] = A + (size_t)(bm + r) * (2 * K) + seg * 8;
        dA[i] = sb + r * ROWA + seg * 16;
    }
    const __nv_bfloat16* srcB[B_OPS];
    uint32_t dB[B_OPS];
    #pragma unroll
    for (int i = 0; i < B_OPS; i++) {
        int idx = tid + i * 256;
        int r = idx >> 4, seg = idx & 15;
        srcB[i] = B + (size_t)r * N + bn + seg * 8;
        dB[i] = sb + OFF_BH + r * ROWB + seg * 16;
    }

    auto issue = [&](int kc, int st) {
        uint32_t so = st * STG;
        #pragma unroll
        for (int i = 0; i < A_OPS; i++) {
            CP16(dA[i] + so, srcA[i] + kc * 32);
            CP16(dA[i] + so + OFF_AL, srcA[i] + K + kc * 32);
        }
        #pragma unroll
        for (int i = 0; i < B_OPS; i++) {
            CP16(dB[i] + so, srcB[i] + (size_t)kc * 32 * N);
            CP16(dB[i] + so + 32 * ROWB, srcB[i] + (size_t)(K + kc * 32) * N);
        }
    };

    issue(0, 0); CP_COMMIT();
    issue(1, 1); CP_COMMIT();

    int grp = lane >> 3, lr = lane & 7;
    uint32_t aoff[2][2];
    #pragma unroll
    for (int ks = 0; ks < 2; ks++)
        #pragma unroll
        for (int ma = 0; ma < 2; ma++)
            aoff[ks][ma] = (wm * 32 + ma * 16 + (grp & 1) * 8 + lr) * ROWA +
                           (ks * 16 + (grp >> 1) * 8) * 2;
    uint32_t boff[2][NAT / 2];
    #pragma unroll
    for (int ks = 0; ks < 2; ks++)
        #pragma unroll
        for (int p = 0; p < NAT / 2; p++)
            boff[ks][p] = OFF_BH + (ks * 16 + lr + (grp & 1) * 8) * ROWB +
                          (wn * WTN + p * 16 + ((lane >> 4) & 1) * 8) * 2;

    int st_c = 0, st_n = 2;
    for (int c = 0; c < nch; c++) {
        CP_WAIT(1);
        __syncthreads();
        if (c + 2 < nch) issue(c + 2, st_n);
        CP_COMMIT();

        uint32_t base = sb + st_c * STG;
        st_c = (st_c == 2) ? 0 : st_c + 1;
        st_n = (st_n == 2) ? 0 : st_n + 1;

        #pragma unroll
        for (int ks = 0; ks < 2; ks++) {
            uint32_t ah[2][4], al[2][4];
            #pragma unroll
            for (int ma = 0; ma < 2; ma++) {
                LDSM4(ah[ma][0], ah[ma][1], ah[ma][2], ah[ma][3], base + aoff[ks][ma]);
                LDSM4(al[ma][0], al[ma][1], al[ma][2], al[ma][3],
                      base + aoff[ks][ma] + OFF_AL);
            }
            #pragma unroll
            for (int p = 0; p < NAT / 2; p++) {
                uint32_t b0[2], b1[2];
                LDSM4T(b0[0], b0[1], b1[0], b1[1], base + boff[ks][p]);
                #pragma unroll
                for (int ma = 0; ma < 2; ma++) {
                    MMA(acc[ma][2 * p],     ah[ma], b0);
                    MMA(acc[ma][2 * p + 1], ah[ma], b1);
                    MMA(acc[ma][2 * p],     al[ma], b0);
                    MMA(acc[ma][2 * p + 1], al[ma], b1);
                }
            }
            #pragma unroll
            for (int p = 0; p < NAT / 2; p++) {
                uint32_t b0[2], b1[2];
                LDSM4T(b0[0], b0[1], b1[0], b1[1], base + boff[ks][p] + 32 * ROWB);
                #pragma unroll
                for (int ma = 0; ma < 2; ma++) {
                    MMA(acc[ma][2 * p],     ah[ma], b0);
                    MMA(acc[ma][2 * p + 1], ah[ma], b1);
                }
            }
        }
    }

    int tr = lane >> 2, tc = (lane & 3) * 2;
    #pragma unroll
    for (int ma = 0; ma < 2; ma++) {
        int row = bm + wm * 32 + ma * 16 + tr;
        #pragma unroll
        for (int na = 0; na < NAT; na++) {
            int col = bn + wn * WTN + na * 8 + tc;
            float2 bv = *(const float2*)(bias + col);
            float v0 = acc[ma][na][0] + bv.x;
            float v1 = acc[ma][na][1] + bv.y;
            float v2 = acc[ma][na][2] + bv.x;
            float v3 = acc[ma][na][3] + bv.y;
            if (MODE == 1) {
                v0 = gelu_tanh(v0); v1 = gelu_tanh(v1);
                v2 = gelu_tanh(v2); v3 = gelu_tanh(v3);
                store_split2(Cs, (size_t)row * 2 * N, col, N, v0, v1);
                store_split2(Cs, (size_t)(row + 8) * 2 * N, col, N, v2, v3);
            } else {
                if (MODE == 2) {
                    float2 gv = *(const float2*)(gate + col);
                    float2 x0 = *(const float2*)(X + (size_t)row * N + col);
                    float2 x1 = *(const float2*)(X + (size_t)(row + 8) * N + col);
                    v0 = x0.x + v0 * gv.x; v1 = x0.y + v1 * gv.y;
                    v2 = x1.x + v2 * gv.x; v3 = x1.y + v3 * gv.y;
                }
                *(float2*)(C + (size_t)row * N + col)       = make_float2(v0, v1);
                *(float2*)(C + (size_t)(row + 8) * N + col) = make_float2(v2, v3);
            }
        }
    }
}

// ---------------- mod/gate precompute ----------------
__global__ void modgate_kernel(const float* __restrict__ cond,
                               const float* __restrict__ a1w, const float* __restrict__ a1b,
                               const float* __restrict__ g1w, const float* __restrict__ g1b,
                               const float* __restrict__ a2w, const float* __restrict__ a2b,
                               const float* __restrict__ g2w, const float* __restrict__ g2b,
                               float* __restrict__ out) {
    __shared__ float cs[D_MODEL];
    for (int i = threadIdx.x; i < D_MODEL; i += blockDim.x) cs[i] = cond[i];
    __syncthreads();
    int o = blockIdx.x * blockDim.x + threadIdx.x;
    int l = o / (6 * D_MODEL);
    int j = o % (6 * D_MODEL);
    const float* W; const float* Bv; int col, ncols;
    if (j < 2 * D_MODEL)      { W = a1w + (size_t)l * D_MODEL * 2 * D_MODEL; Bv = a1b + l * 2 * D_MODEL; col = j;               ncols = 2 * D_MODEL; }
    else if (j < 3 * D_MODEL) { W = g1w + (size_t)l * D_MODEL * D_MODEL;     Bv = g1b + l * D_MODEL;     col = j - 2 * D_MODEL; ncols = D_MODEL; }
    else if (j < 5 * D_MODEL) { W = a2w + (size_t)l * D_MODEL * 2 * D_MODEL; Bv = a2b + l * 2 * D_MODEL; col = j - 3 * D_MODEL; ncols = 2 * D_MODEL; }
    else                      { W = g2w + (size_t)l * D_MODEL * D_MODEL;     Bv = g2b + l * D_MODEL;     col = j - 5 * D_MODEL; ncols = D_MODEL; }
    float acc = 0.f;
    #pragma unroll 8
    for (int d = 0; d < D_MODEL; d++) acc += cs[d] * W[(size_t)d * ncols + col];
    out[o] = acc + Bv[col];
}

// ---------------- LayerNorm + adaLN modulation, fused bf16 split out ----------------
__global__ void ln_mod_kernel(const float* __restrict__ x,
                              const float* __restrict__ shift,
                              const float* __restrict__ scale,
                              __nv_bfloat16* __restrict__ out) {
    int row = blockIdx.x;
    int tid = threadIdx.x;
    const float* xr = x + (size_t)row * D_MODEL;
    float v[4], s = 0.f, s2 = 0.f;
    #pragma unroll
    for (int i = 0; i < 4; i++) {
        v[i] = xr[tid + i * 256];
        s += v[i]; s2 += v[i] * v[i];
    }
    #pragma unroll
    for (int off = 16; off; off >>= 1) {
        s  += __shfl_xor_sync(0xffffffff, s,  off);
        s2 += __shfl_xor_sync(0xffffffff, s2, off);
    }
    __shared__ float sh1[8], sh2[8];
    int w = tid >> 5, lane = tid & 31;
    if (lane == 0) { sh1[w] = s; sh2[w] = s2; }
    __syncthreads();
    if (tid == 0) {
        float a = 0.f, b = 0.f;
        #pragma unroll
        for (int i = 0; i < 8; i++) { a += sh1[i]; b += sh2[i]; }
        sh1[0] = a; sh2[0] = b;
    }
    __syncthreads();
    float mean = sh1[0] * (1.f / D_MODEL);
    float var  = sh2[0] * (1.f / D_MODEL) - mean * mean;
    float r = rsqrtf(var + 1e-5f);
    __nv_bfloat16* orow = out + (size_t)row * 2 * D_MODEL;
    #pragma unroll
    for (int i = 0; i < 4; i++) {
        int col = tid + i * 256;
        float hv = (v[i] - mean) * r * (1.f + scale[col]) + shift[col];
        __nv_bfloat16 hi = __float2bfloat16(hv);
        orow[col]           = hi;
        orow[D_MODEL + col] = __float2bfloat16(hv - __bfloat162float(hi));
    }
}

// ---------------- RoPE table (fp64 once) ----------------
__global__ void rope_table_kernel(float* __restrict__ rc, float* __restrict__ rs) {
    int idx = blockIdx.x * 256 + threadIdx.x;
    int s = idx >> 5, j = idx & 31;
    double inv = exp(-((double)j / 32.0) * 9.210340371976184);
    double ang = (double)s * inv;
    rc[idx] = (float)cos(ang);
    rs[idx] = (float)sin(ang);
}

// ---------------- per-(token,head) RMSNorm + RoPE ----------------
__global__ void rmsrope_kernel(float* __restrict__ qkv,
                               const float* __restrict__ rc,
                               const float* __restrict__ rs) {
    int s = blockIdx.x;
    int warp = threadIdx.x >> 5, lane = threadIdx.x & 31;
    int hh = blockIdx.y * 8 + warp;
    int which = hh >> 4;
    int h = hh & 15;
    float* base = qkv + (size_t)s * 3 * D_MODEL + which * D_MODEL + h * DH;
    float x1 = base[lane], x2 = base[lane + 32];
    float ss = x1 * x1 + x2 * x2;
    #pragma unroll
    for (int off = 16; off; off >>= 1) ss += __shfl_xor_sync(0xffffffff, ss, off);
    float r = rsqrtf(ss * (1.f / DH) + 1e-6f);
    x1 *= r; x2 *= r;
    float c = rc[s * 32 + lane], sn = rs[s * 32 + lane];
    base[lane]      = x1 * c - x2 * sn;
    base[lane + 32] = x1 * sn + x2 * c;
}

// ---------------- local (window=8) per-frame flash attention ----------------
__global__ void __launch_bounds__(256, 4)
attn_kernel(const float* __restrict__ qkv, __nv_bfloat16* __restrict__ Oa, int window) {
    int f = blockIdx.x;
    int h = blockIdx.y;
    int tid = threadIdx.x;
    int warp = tid >> 5, lane = tid & 31;
    __shared__ float Qs[8][DH];
    __shared__ float Ks[32][DH + 4];
    __shared__ float Vs[32][DH + 2];
    int h0 = h * DH;
    int qrow0 = f * TPF;
    for (int i = tid; i < 8 * DH; i += 256) {
        int r = i >> 6, d = i & 63;
        Qs[r][d] = qkv[(size_t)(qrow0 + r) * 3 * D_MODEL + h0 + d];
    }
    __syncthreads();

    int fstart = max(0, f - window + 1);
    int kstart = fstart * TPF;
    int kend = (f + 1) * TPF;
    int nk = kend - kstart;

    float m = -1e30f, l = 0.f;
    float o0 = 0.f, o1 = 0.f;
    int q = warp;
    int d0 = lane * 2;
    const float sc = 0.125f;

    for (int c0 = 0; c0 < nk; c0 += 32) {
        for (int i = tid; i < 32 * DH; i += 256) {
            int r = i >> 6, d = i & 63;
            int kr = kstart + c0 + r;
            if (kr > S_LEN - 1) kr = S_LEN - 1;
            Ks[r][d] = qkv[(size_t)kr * 3 * D_MODEL + D_MODEL + h0 + d];
            Vs[r][d] = qkv[(size_t)kr * 3 * D_MODEL + 2 * D_MODEL + h0 + d];
        }
        __syncthreads();

        float s;
        if (c0 + lane < nk) {
            float a0 = 0.f, a1 = 0.f, a2 = 0.f, a3 = 0.f;
            #pragma unroll
            for (int d = 0; d < DH; d += 4) {
                a0 = fmaf(Qs[q][d],     Ks[lane][d],     a0);
                a1 = fmaf(Qs[q][d + 1], Ks[lane][d + 1], a1);
                a2 = fmaf(Qs[q][d + 2], Ks[lane][d + 2], a2);
                a3 = fmaf(Qs[q][d + 3], Ks[lane][d + 3], a3);
            }
            s = (a0 + a1 + a2 + a3) * sc;
        } else {
            s = -1e30f;
        }
        float cm = s;
        #pragma unroll
        for (int off = 16; off; off >>= 1) cm = fmaxf(cm, __shfl_xor_sync(0xffffffff, cm, off));
        float mnew = fmaxf(m, cm);
        float p = __expf(s - mnew);
        if (c0 + lane >= nk) p = 0.f;
        float ps = p;
        #pragma unroll
        for (int off = 16; off; off >>= 1) ps += __shfl_xor_sync(0xffffffff, ps, off);
        float factor = __expf(m - mnew);
        l = l * factor + ps;
        m = mnew;
        o0 *= factor; o1 *= factor;
        #pragma unroll
        for (int k = 0; k < 32; k++) {
            float pk = __shfl_sync(0xffffffff, p, k);
            o0 = fmaf(pk, Vs[k][d0],     o0);
            o1 = fmaf(pk, Vs[k][d0 + 1], o1);
        }
        __syncthreads();
    }
    float invl = 1.f / l;
    float a = o0 * invl, b = o1 * invl;
    __nv_bfloat162 hi, lo;
    hi.x = __float2bfloat16(a);
    hi.y = __float2bfloat16(b);
    lo.x = __float2bfloat16(a - __bfloat162float(hi.x));
    lo.y = __float2bfloat16(b - __bfloat162float(hi.y));
    size_t rb = (size_t)(qrow0 + q) * 2 * D_MODEL;
    *(__nv_bfloat162*)(Oa + rb + h0 + d0)           = hi;
    *(__nv_bfloat162*)(Oa + rb + D_MODEL + h0 + d0) = lo;
}

// ---------------- global (window=128) attention: 4 frames / block (K/V reuse) ----------------
__global__ void __launch_bounds__(256, 4)
attn_kernel_blk(const float* __restrict__ qkv, __nv_bfloat16* __restrict__ Oa, int window) {
    int F0 = blockIdx.x * QBLK;
    int h = blockIdx.y;
    int tid = threadIdx.x;
    int warp = tid >> 5, lane = tid & 31;
    __shared__ float Qs[QROWS][DH];
    __shared__ float Ks[32][DH + 4];
    __shared__ float Vs[32][DH + 2];
    int h0 = h * DH;
    int qrow0 = F0 * TPF;
    for (int i = tid; i < QROWS * DH; i += 256) {
        int r = i >> 6, d = i & 63;
        Qs[r][d] = qkv[(size_t)(qrow0 + r) * 3 * D_MODEL + h0 + d];
    }
    __syncthreads();

    int kstart = max(0, F0 - window + 1) * TPF;
    int kend = (F0 + QBLK) * TPF;
    int nk = kend - kstart;

    float m[QBLK], l[QBLK], o0[QBLK], o1[QBLK];
    #pragma unroll
    for (int qi = 0; qi < QBLK; qi++) { m[qi] = -1e30f; l[qi] = 0.f; o0[qi] = 0.f; o1[qi] = 0.f; }
    int d0 = lane * 2;
    const float sc = 0.125f;

    for (int c0 = 0; c0 < nk; c0 += 32) {
        for (int i = tid; i < 32 * DH; i += 256) {
            int r = i >> 6, d = i & 63;
            int kr = kstart + c0 + r;
            if (kr > S_LEN - 1) kr = S_LEN - 1;
            Ks[r][d] = qkv[(size_t)kr * 3 * D_MODEL + D_MODEL + h0 + d];
            Vs[r][d] = qkv[(size_t)kr * 3 * D_MODEL + 2 * D_MODEL + h0 + d];
        }
        __syncthreads();

        int kr = kstart + c0 + lane;
        int fk = kr >> 3;
        bool inrange = (c0 + lane < nk);

        #pragma unroll
        for (int qi = 0; qi < QBLK; qi++) {
            int q = warp + 8 * qi;
            int fq = F0 + qi;
            bool valid = inrange && (fk <= fq) && (fq - fk < window);
            float s;
            {
                float a0 = 0.f, a1 = 0.f, a2 = 0.f, a3 = 0.f;
                #pragma unroll
                for (int d = 0; d < DH; d += 4) {
                    a0 = fmaf(Qs[q][d],     Ks[lane][d],     a0);
                    a1 = fmaf(Qs[q][d + 1], Ks[lane][d + 1], a1);
                    a2 = fmaf(Qs[q][d + 2], Ks[lane][d + 2], a2);
                    a3 = fmaf(Qs[q][d + 3], Ks[lane][d + 3], a3);
                }
                s = valid ? (a0 + a1 + a2 + a3) * sc : -1e30f;
            }
            float cm = s;
            #pragma unroll
            for (int off = 16; off; off >>= 1)
                cm = fmaxf(cm, __shfl_xor_sync(0xffffffff, cm, off));
            float mnew = fmaxf(m[qi], cm);
            float p = valid ? __expf(s - mnew) : 0.f;
            float ps = p;
            #pragma unroll
            for (int off = 16; off; off >>= 1)
                ps += __shfl_xor_sync(0xffffffff, ps, off);
            float factor = __expf(m[qi] - mnew);
            l[qi] = l[qi] * factor + ps;
            m[qi] = mnew;
            o0[qi] *= factor; o1[qi] *= factor;
            #pragma unroll
            for (int k = 0; k < 32; k++) {
                float pk = __shfl_sync(0xffffffff, p, k);
                o0[qi] = fmaf(pk, Vs[k][d0],     o0[qi]);
                o1[qi] = fmaf(pk, Vs[k][d0 + 1], o1[qi]);
            }
        }
        __syncthreads();
    }

    #pragma unroll
    for (int qi = 0; qi < QBLK; qi++) {
        float invl = 1.f / l[qi];
        float a = o0[qi] * invl, b = o1[qi] * invl;
        __nv_bfloat162 hi, lo;
        hi.x = __float2bfloat16(a);
        hi.y = __float2bfloat16(b);
        lo.x = __float2bfloat16(a - __bfloat162float(hi.x));
        lo.y = __float2bfloat16(b - __bfloat162float(hi.y));
        size_t rb = (size_t)(qrow0 + warp + 8 * qi) * 2 * D_MODEL;
        *(__nv_bfloat162*)(Oa + rb + h0 + d0)           = hi;
        *(__nv_bfloat162*)(Oa + rb + D_MODEL + h0 + d0) = lo;
    }
}

// ---------------- host-side orchestration ----------------
extern "C" void kernel_launch(void* const* d_in, const int* in_sizes, int n_in,
                              void* d_out, int out_size) {
    const float* x       = (const float*)d_in[0];
    const float* cond    = (const float*)d_in[1];
    const float* qkv_w   = (const float*)d_in[2];
    const float* qkv_b   = (const float*)d_in[3];
    const float* out_w   = (const float*)d_in[4];
    const float* out_b   = (const float*)d_in[5];
    const float* mlp_w1  = (const float*)d_in[6];
    const float* mlp_b1  = (const float*)d_in[7];
    const float* mlp_w2  = (const float*)d_in[8];
    const float* mlp_b2  = (const float*)d_in[9];
    const float* ada1_w  = (const float*)d_in[10];
    const float* ada1_b  = (const float*)d_in[11];
    const float* gate1_w = (const float*)d_in[12];
    const float* gate1_b = (const float*)d_in[13];
    const float* ada2_w  = (const float*)d_in[14];
    const float* ada2_b  = (const float*)d_in[15];
    const float* gate2_w = (const float*)d_in[16];
    const float* gate2_b = (const float*)d_in[17];
    float* X = (float*)d_out;

    float *qkv_ptr, *mod_ptr, *rc_ptr, *rs_ptr;
    __nv_bfloat16 *abuf, *abuf2, *wbuf;
    cudaGetSymbolAddress((void**)&qkv_ptr, g_qkv);
    cudaGetSymbolAddress((void**)&mod_ptr, g_mod);
    cudaGetSymbolAddress((void**)&rc_ptr,  g_ropec);
    cudaGetSymbolAddress((void**)&rs_ptr,  g_ropes);
    cudaGetSymbolAddress((void**)&abuf,    g_abuf);
    cudaGetSymbolAddress((void**)&abuf2,   g_abuf2);
    cudaGetSymbolAddress((void**)&wbuf,    g_wbuf);

    const int SM128 = (2 * 128 * 80 + 2 * 32 * 272) * 3;  // 113664
    const int SM64  = (2 * 64 * 80 + 2 * 32 * 272) * 3;   // 82944
    cudaFuncSetAttribute(mma_gemm<0, 128>, cudaFuncAttributeMaxDynamicSharedMemorySize, SM128);
    cudaFuncSetAttribute(mma_gemm<1, 128>, cudaFuncAttributeMaxDynamicSharedMemorySize, SM128);
    cudaFuncSetAttribute(mma_gemm<2, 64>,  cudaFuncAttributeMaxDynamicSharedMemorySize, SM64);

    cudaMemcpyAsync(X, x, (size_t)S_LEN * D_MODEL * sizeof(float), cudaMemcpyDeviceToDevice);

    rope_table_kernel<<<S_LEN * 32 / 256, 256>>>(rc_ptr, rs_ptr);

    modgate_kernel<<<L_LAYERS * 6 * D_MODEL / 256, 256>>>(
        cond, ada1_w, ada1_b, gate1_w, gate1_b, ada2_w, ada2_b, gate2_w, gate2_b, mod_ptr);

    for (int i = 0; i < L_LAYERS; i++) {
        const float* mod = mod_ptr + i * 6 * D_MODEL;
        int window = (i % 4 == 0) ? 128 : 8;

        // ---- attention block ----
        ln_mod_kernel<<<S_LEN, 256>>>(X, mod, mod + D_MODEL, abuf);

        split_w_kernel<<<dim3(3 * D_MODEL / 1024, D_MODEL), 256>>>(
            qkv_w + (size_t)i * D_MODEL * 3 * D_MODEL, wbuf, D_MODEL, 3 * D_MODEL);
        mma_gemm<0, 128><<<dim3(3 * D_MODEL / 128, S_LEN / 128), 256, SM128>>>(
            abuf, wbuf, qkv_b + i * 3 * D_MODEL, nullptr, qkv_ptr, nullptr, nullptr,
            S_LEN, 3 * D_MODEL, D_MODEL);

        rmsrope_kernel<<<dim3(S_LEN, 4), 256>>>(qkv_ptr, rc_ptr, rs_ptr);
        if (window > 8) {
            attn_kernel_blk<<<dim3(NFRAMES / QBLK, NH), 256>>>(qkv_ptr, abuf, window);
        } else {
            attn_kernel<<<dim3(NFRAMES, NH), 256>>>(qkv_ptr, abuf, window);
        }

        split_w_kernel<<<dim3(D_MODEL / 1024, D_MODEL), 256>>>(
            out_w + (size_t)i * D_MODEL * D_MODEL, wbuf, D_MODEL, D_MODEL);
        mma_gemm<2, 64><<<dim3(D_MODEL / 128, S_LEN / 64), 256, SM64>>>(
            abuf, wbuf, out_b + i * D_MODEL, mod + 2 * D_MODEL, X, nullptr, X,
            S_LEN, D_MODEL, D_MODEL);

        // ---- MLP block ----
        ln_mod_kernel<<<S_LEN, 256>>>(X, mod + 3 * D_MODEL, mod + 4 * D_MODEL, abuf);

        split_w_kernel<<<dim3(DFF / 1024, D_MODEL), 256>>>(
            mlp_w1 + (size_t)i * D_MODEL * DFF, wbuf, D_MODEL, DFF);
        mma_gemm<1, 128><<<dim3(DFF / 128, S_LEN / 128), 256, SM128>>>(
            abuf, wbuf, mlp_b1 + i * DFF, nullptr, nullptr, abuf2, nullptr,
            S_LEN, DFF, D_MODEL);

        split_w_kernel<<<dim3(D_MODEL / 1024, DFF), 256>>>(
            mlp_w2 + (size_t)i * DFF * D_MODEL, wbuf, DFF, D_MODEL);
        mma_gemm<2, 64><<<dim3(D_MODEL / 128, S_LEN / 64), 256, SM64>>>(
            abuf2, wbuf, mlp_b2 + i * D_MODEL, mod + 5 * D_MODEL, X, nullptr, X,
            S_LEN, D_MODEL, DFF);
    }
}

// round 17
// speedup vs baseline: 1.1877x; 1.1245x over previous
#include <cuda_runtime.h>
#include <cuda_bf16.h>
#include <math.h>
#include <stdint.h>

#define S_LEN 1024
#define D_MODEL 1024
#define NH 16
#define DH 64
#define L_LAYERS 4
#define DFF 4096
#define TPF 8
#define NFRAMES (S_LEN / TPF)

// ---------------- scratch (device globals; no allocation) ----------------
__device__ float g_qkv[S_LEN * 3 * D_MODEL];
__device__ float g_mod[L_LAYERS * 6 * D_MODEL];
__device__ float g_ropec[S_LEN * 32];
__device__ float g_ropes[S_LEN * 32];
__device__ __nv_bfloat16 g_abuf[1024 * 2048];
__device__ __nv_bfloat16 g_abuf2[1024 * 8192];
__device__ __nv_bfloat16 g_wbuf[8192 * 1024];

// ---------------- helpers ----------------
__device__ __forceinline__ uint32_t smem_u32(const void* p) {
    uint32_t a;
    asm("{ .reg .u64 t; cvta.to.shared.u64 t, %1; cvt.u32.u64 %0, t; }" : "=r"(a) : "l"(p));
    return a;
}
#define CP16(dst, src) \
    asm volatile("cp.async.cg.shared.global [%0], [%1], 16;" :: "r"(dst), "l"(src))
#define CP_COMMIT() asm volatile("cp.async.commit_group;")
#define CP_WAIT(n)  asm volatile("cp.async.wait_group %0;" :: "n"(n))
#define LDSM4(r0, r1, r2, r3, addr)                                        \
    asm volatile("ldmatrix.sync.aligned.m8n8.x4.shared.b16 {%0,%1,%2,%3}, [%4];" \
        : "=r"(r0), "=r"(r1), "=r"(r2), "=r"(r3) : "r"(addr))
#define LDSM4T(r0, r1, r2, r3, addr)                                       \
    asm volatile("ldmatrix.sync.aligned.m8n8.x4.trans.shared.b16 {%0,%1,%2,%3}, [%4];" \
        : "=r"(r0), "=r"(r1), "=r"(r2), "=r"(r3) : "r"(addr))
#define MMA(acc, ar, br)                                                   \
    asm volatile(                                                          \
        "mma.sync.aligned.m16n8k16.row.col.f32.bf16.bf16.f32 "             \
        "{%0,%1,%2,%3}, {%4,%5,%6,%7}, {%8,%9}, {%0,%1,%2,%3};"            \
        : "+f"((acc)[0]), "+f"((acc)[1]), "+f"((acc)[2]), "+f"((acc)[3])   \
        : "r"((ar)[0]), "r"((ar)[1]), "r"((ar)[2]), "r"((ar)[3]),          \
          "r"((br)[0]), "r"((br)[1]))

__device__ __forceinline__ float gelu_tanh(float v) {
    float t = tanhf(0.7978845608028654f * (v + 0.044715f * v * v * v));
    return 0.5f * v * (1.f + t);
}

__device__ __forceinline__ void store_split2(__nv_bfloat16* Cs, size_t rowbase, int col,
                                             int N, float a, float b) {
    __nv_bfloat162 hi, lo;
    hi.x = __float2bfloat16(a);
    hi.y = __float2bfloat16(b);
    lo.x = __float2bfloat16(a - __bfloat162float(hi.x));
    lo.y = __float2bfloat16(b - __bfloat162float(hi.y));
    *(__nv_bfloat162*)(Cs + rowbase + col)     = hi;
    *(__nv_bfloat162*)(Cs + rowbase + N + col) = lo;
}

// ---------------- weight split: W [K,N] fp32 -> [2K,N] bf16 (hi rows | lo rows) ----------------
__global__ void split_w_kernel(const float* __restrict__ W, __nv_bfloat16* __restrict__ out,
                               int K, int N) {
    int n0 = blockIdx.x * 1024 + threadIdx.x * 4;
    int k = blockIdx.y;
    float4 w = *(const float4*)(W + (size_t)k * N + n0);
    __nv_bfloat162 h0, h1, l0, l1;
    h0.x = __float2bfloat16(w.x); h0.y = __float2bfloat16(w.y);
    h1.x = __float2bfloat16(w.z); h1.y = __float2bfloat16(w.w);
    l0.x = __float2bfloat16(w.x - __bfloat162float(h0.x));
    l0.y = __float2bfloat16(w.y - __bfloat162float(h0.y));
    l1.x = __float2bfloat16(w.z - __bfloat162float(h1.x));
    l1.y = __float2bfloat16(w.w - __bfloat162float(h1.y));
    uint2 hu, lu;
    hu.x = *(uint32_t*)&h0; hu.y = *(uint32_t*)&h1;
    lu.x = *(uint32_t*)&l0; lu.y = *(uint32_t*)&l1;
    *(uint2*)(out + (size_t)k * N + n0)       = hu;
    *(uint2*)(out + (size_t)(K + k) * N + n0) = lu;
}

// ---------------- mma.sync bf16 3-term GEMM, multi-stage pipeline, 1 sync/chunk ----------------
// STAGES = 4 for BM=64 (deep-K GEMMs), 3 for BM=128 (SMEM ceiling).
template <int MODE, int BM>
__global__ void __launch_bounds__(256, 2)
mma_gemm(const __nv_bfloat16* __restrict__ A, const __nv_bfloat16* __restrict__ B,
         const float* __restrict__ bias, const float* __restrict__ gate,
         float* __restrict__ C, __nv_bfloat16* __restrict__ Cs,
         const float* __restrict__ X, int M, int N, int K) {
    constexpr int WARPS_M = BM / 32;
    constexpr int WARPS_N = 8 / WARPS_M;
    constexpr int WTN = 128 / WARPS_N;
    constexpr int NAT = WTN / 8;
    constexpr int ROWA = 80;
    constexpr int ROWB = 272;
    constexpr int OFF_AL = BM * ROWA;
    constexpr int OFF_BH = 2 * BM * ROWA;
    constexpr int STG = 2 * BM * ROWA + 2 * 32 * ROWB;
    constexpr int A_OPS = BM / 64;
    constexpr int B_OPS = 2;
    constexpr int STAGES = (BM == 64) ? 4 : 3;

    extern __shared__ __align__(128) char dyn[];
    uint32_t sb = smem_u32(dyn);
    int tid = threadIdx.x;
    int wid = tid >> 5, lane = tid & 31;
    int wm = wid / WARPS_N, wn = wid % WARPS_N;
    int bm = blockIdx.y * BM, bn = blockIdx.x * 128;

    float acc[2][NAT][4];
    #pragma unroll
    for (int i = 0; i < 2; i++)
        #pragma unroll
        for (int j = 0; j < NAT; j++)
            #pragma unroll
            for (int q = 0; q < 4; q++) acc[i][j][q] = 0.f;

    int nch = K >> 5;

    const __nv_bfloat16* srcA[A_OPS];
    uint32_t dA[A_OPS];
    #pragma unroll
    for (int i = 0; i < A_OPS; i++) {
        int idx = tid + i * 256;
        int r = idx >> 2, seg = idx & 3;
        srcA[i] = A + (size_t)(bm + r) * (2 * K) + seg * 8;
        dA[i] = sb + r * ROWA + seg * 16;
    }
    const __nv_bfloat16* srcB[B_OPS];
    uint32_t dB[B_OPS];
    #pragma unroll
    for (int i = 0; i < B_OPS; i++) {
        int idx = tid + i * 256;
        int r = idx >> 4, seg = idx & 15;
        srcB[i] = B + (size_t)r * N + bn + seg * 8;
        dB[i] = sb + OFF_BH + r * ROWB + seg * 16;
    }

    auto issue = [&](int kc, int st) {
        uint32_t so = st * STG;
        #pragma unroll
        for (int i = 0; i < A_OPS; i++) {
            CP16(dA[i] + so, srcA[i] + kc * 32);
            CP16(dA[i] + so + OFF_AL, srcA[i] + K + kc * 32);
        }
        #pragma unroll
        for (int i = 0; i < B_OPS; i++) {
            CP16(dB[i] + so, srcB[i] + (size_t)kc * 32 * N);
            CP16(dB[i] + so + 32 * ROWB, srcB[i] + (size_t)(K + kc * 32) * N);
        }
    };

    // prologue: chunks 0..STAGES-2 into stages 0..STAGES-2
    #pragma unroll
    for (int s = 0; s < STAGES - 1; s++) {
        issue(s, s); CP_COMMIT();
    }

    int grp = lane >> 3, lr = lane & 7;
    uint32_t aoff[2][2];
    #pragma unroll
    for (int ks = 0; ks < 2; ks++)
        #pragma unroll
        for (int ma = 0; ma < 2; ma++)
            aoff[ks][ma] = (wm * 32 + ma * 16 + (grp & 1) * 8 + lr) * ROWA +
                           (ks * 16 + (grp >> 1) * 8) * 2;
    uint32_t boff[2][NAT / 2];
    #pragma unroll
    for (int ks = 0; ks < 2; ks++)
        #pragma unroll
        for (int p = 0; p < NAT / 2; p++)
            boff[ks][p] = OFF_BH + (ks * 16 + lr + (grp & 1) * 8) * ROWB +
                          (wn * WTN + p * 16 + ((lane >> 4) & 1) * 8) * 2;

    int st_c = 0, st_n = STAGES - 1;
    for (int c = 0; c < nch; c++) {
        CP_WAIT(STAGES - 2);
        __syncthreads();   // chunk c landed; all warps done with stage st_n's old chunk
        if (c + STAGES - 1 < nch) issue(c + STAGES - 1, st_n);
        CP_COMMIT();

        uint32_t base = sb + st_c * STG;
        st_c = (st_c + 1 == STAGES) ? 0 : st_c + 1;
        st_n = (st_n + 1 == STAGES) ? 0 : st_n + 1;

        #pragma unroll
        for (int ks = 0; ks < 2; ks++) {
            uint32_t ah[2][4], al[2][4];
            #pragma unroll
            for (int ma = 0; ma < 2; ma++) {
                LDSM4(ah[ma][0], ah[ma][1], ah[ma][2], ah[ma][3], base + aoff[ks][ma]);
                LDSM4(al[ma][0], al[ma][1], al[ma][2], al[ma][3],
                      base + aoff[ks][ma] + OFF_AL);
            }
            #pragma unroll
            for (int p = 0; p < NAT / 2; p++) {
                uint32_t b0[2], b1[2];
                LDSM4T(b0[0], b0[1], b1[0], b1[1], base + boff[ks][p]);
                #pragma unroll
                for (int ma = 0; ma < 2; ma++) {
                    MMA(acc[ma][2 * p],     ah[ma], b0);
                    MMA(acc[ma][2 * p + 1], ah[ma], b1);
                    MMA(acc[ma][2 * p],     al[ma], b0);
                    MMA(acc[ma][2 * p + 1], al[ma], b1);
                }
            }
            #pragma unroll
            for (int p = 0; p < NAT / 2; p++) {
                uint32_t b0[2], b1[2];
                LDSM4T(b0[0], b0[1], b1[0], b1[1], base + boff[ks][p] + 32 * ROWB);
                #pragma unroll
                for (int ma = 0; ma < 2; ma++) {
                    MMA(acc[ma][2 * p],     ah[ma], b0);
                    MMA(acc[ma][2 * p + 1], ah[ma], b1);
                }
            }
        }
    }

    int tr = lane >> 2, tc = (lane & 3) * 2;
    #pragma unroll
    for (int ma = 0; ma < 2; ma++) {
        int row = bm + wm * 32 + ma * 16 + tr;
        #pragma unroll
        for (int na = 0; na < NAT; na++) {
            int col = bn + wn * WTN + na * 8 + tc;
            float2 bv = *(const float2*)(bias + col);
            float v0 = acc[ma][na][0] + bv.x;
            float v1 = acc[ma][na][1] + bv.y;
            float v2 = acc[ma][na][2] + bv.x;
            float v3 = acc[ma][na][3] + bv.y;
            if (MODE == 1) {
                v0 = gelu_tanh(v0); v1 = gelu_tanh(v1);
                v2 = gelu_tanh(v2); v3 = gelu_tanh(v3);
                store_split2(Cs, (size_t)row * 2 * N, col, N, v0, v1);
                store_split2(Cs, (size_t)(row + 8) * 2 * N, col, N, v2, v3);
            } else {
                if (MODE == 2) {
                    float2 gv = *(const float2*)(gate + col);
                    float2 x0 = *(const float2*)(X + (size_t)row * N + col);
                    float2 x1 = *(const float2*)(X + (size_t)(row + 8) * N + col);
                    v0 = x0.x + v0 * gv.x; v1 = x0.y + v1 * gv.y;
                    v2 = x1.x + v2 * gv.x; v3 = x1.y + v3 * gv.y;
                }
                *(float2*)(C + (size_t)row * N + col)       = make_float2(v0, v1);
                *(float2*)(C + (size_t)(row + 8) * N + col) = make_float2(v2, v3);
            }
        }
    }
}

// ---------------- mod/gate precompute ----------------
__global__ void modgate_kernel(const float* __restrict__ cond,
                               const float* __restrict__ a1w, const float* __restrict__ a1b,
                               const float* __restrict__ g1w, const float* __restrict__ g1b,
                               const float* __restrict__ a2w, const float* __restrict__ a2b,
                               const float* __restrict__ g2w, const float* __restrict__ g2b,
                               float* __restrict__ out) {
    __shared__ float cs[D_MODEL];
    for (int i = threadIdx.x; i < D_MODEL; i += blockDim.x) cs[i] = cond[i];
    __syncthreads();
    int o = blockIdx.x * blockDim.x + threadIdx.x;
    int l = o / (6 * D_MODEL);
    int j = o % (6 * D_MODEL);
    const float* W; const float* Bv; int col, ncols;
    if (j < 2 * D_MODEL)      { W = a1w + (size_t)l * D_MODEL * 2 * D_MODEL; Bv = a1b + l * 2 * D_MODEL; col = j;               ncols = 2 * D_MODEL; }
    else if (j < 3 * D_MODEL) { W = g1w + (size_t)l * D_MODEL * D_MODEL;     Bv = g1b + l * D_MODEL;     col = j - 2 * D_MODEL; ncols = D_MODEL; }
    else if (j < 5 * D_MODEL) { W = a2w + (size_t)l * D_MODEL * 2 * D_MODEL; Bv = a2b + l * 2 * D_MODEL; col = j - 3 * D_MODEL; ncols = 2 * D_MODEL; }
    else                      { W = g2w + (size_t)l * D_MODEL * D_MODEL;     Bv = g2b + l * D_MODEL;     col = j - 5 * D_MODEL; ncols = D_MODEL; }
    float acc = 0.f;
    #pragma unroll 8
    for (int d = 0; d < D_MODEL; d++) acc += cs[d] * W[(size_t)d * ncols + col];
    out[o] = acc + Bv[col];
}

// ---------------- LayerNorm + adaLN modulation, fused bf16 split out ----------------
__global__ void ln_mod_kernel(const float* __restrict__ x,
                              const float* __restrict__ shift,
                              const float* __restrict__ scale,
                              __nv_bfloat16* __restrict__ out) {
    int row = blockIdx.x;
    int tid = threadIdx.x;
    const float* xr = x + (size_t)row * D_MODEL;
    float v[4], s = 0.f, s2 = 0.f;
    #pragma unroll
    for (int i = 0; i < 4; i++) {
        v[i] = xr[tid + i * 256];
        s += v[i]; s2 += v[i] * v[i];
    }
    #pragma unroll
    for (int off = 16; off; off >>= 1) {
        s  += __shfl_xor_sync(0xffffffff, s,  off);
        s2 += __shfl_xor_sync(0xffffffff, s2, off);
    }
    __shared__ float sh1[8], sh2[8];
    int w = tid >> 5, lane = tid & 31;
    if (lane == 0) { sh1[w] = s; sh2[w] = s2; }
    __syncthreads();
    if (tid == 0) {
        float a = 0.f, b = 0.f;
        #pragma unroll
        for (int i = 0; i < 8; i++) { a += sh1[i]; b += sh2[i]; }
        sh1[0] = a; sh2[0] = b;
    }
    __syncthreads();
    float mean = sh1[0] * (1.f / D_MODEL);
    float var  = sh2[0] * (1.f / D_MODEL) - mean * mean;
    float r = rsqrtf(var + 1e-5f);
    __nv_bfloat16* orow = out + (size_t)row * 2 * D_MODEL;
    #pragma unroll
    for (int i = 0; i < 4; i++) {
        int col = tid + i * 256;
        float hv = (v[i] - mean) * r * (1.f + scale[col]) + shift[col];
        __nv_bfloat16 hi = __float2bfloat16(hv);
        orow[col]           = hi;
        orow[D_MODEL + col] = __float2bfloat16(hv - __bfloat162float(hi));
    }
}

// ---------------- RoPE table (fp64 once) ----------------
__global__ void rope_table_kernel(float* __restrict__ rc, float* __restrict__ rs) {
    int idx = blockIdx.x * 256 + threadIdx.x;
    int s = idx >> 5, j = idx & 31;
    double inv = exp(-((double)j / 32.0) * 9.210340371976184);
    double ang = (double)s * inv;
    rc[idx] = (float)cos(ang);
    rs[idx] = (float)sin(ang);
}

// ---------------- per-(token,head) RMSNorm + RoPE ----------------
__global__ void rmsrope_kernel(float* __restrict__ qkv,
                               const float* __restrict__ rc,
                               const float* __restrict__ rs) {
    int s = blockIdx.x;
    int warp = threadIdx.x >> 5, lane = threadIdx.x & 31;
    int hh = blockIdx.y * 8 + warp;
    int which = hh >> 4;
    int h = hh & 15;
    float* base = qkv + (size_t)s * 3 * D_MODEL + which * D_MODEL + h * DH;
    float x1 = base[lane], x2 = base[lane + 32];
    float ss = x1 * x1 + x2 * x2;
    #pragma unroll
    for (int off = 16; off; off >>= 1) ss += __shfl_xor_sync(0xffffffff, ss, off);
    float r = rsqrtf(ss * (1.f / DH) + 1e-6f);
    x1 *= r; x2 *= r;
    float c = rc[s * 32 + lane], sn = rs[s * 32 + lane];
    base[lane]      = x1 * c - x2 * sn;
    base[lane + 32] = x1 * sn + x2 * c;
}

// ---------------- frame-masked flash attention, fused bf16 split output ----------------
__global__ void __launch_bounds__(256, 4)
attn_kernel(const float* __restrict__ qkv, __nv_bfloat16* __restrict__ Oa, int window) {
    int f = blockIdx.x;
    int h = blockIdx.y;
    int tid = threadIdx.x;
    int warp = tid >> 5, lane = tid & 31;
    __shared__ float Qs[8][DH];
    __shared__ float Ks[32][DH + 4];
    __shared__ float Vs[32][DH + 2];
    int h0 = h * DH;
    int qrow0 = f * TPF;
    for (int i = tid; i < 8 * DH; i += 256) {
        int r = i >> 6, d = i & 63;
        Qs[r][d] = qkv[(size_t)(qrow0 + r) * 3 * D_MODEL + h0 + d];
    }
    __syncthreads();

    int fstart = max(0, f - window + 1);
    int kstart = fstart * TPF;
    int kend = (f + 1) * TPF;
    int nk = kend - kstart;

    float m = -1e30f, l = 0.f;
    float o0 = 0.f, o1 = 0.f;
    int q = warp;
    int d0 = lane * 2;
    const float sc = 0.125f;

    for (int c0 = 0; c0 < nk; c0 += 32) {
        for (int i = tid; i < 32 * DH; i += 256) {
            int r = i >> 6, d = i & 63;
            int kr = kstart + c0 + r;
            if (kr > S_LEN - 1) kr = S_LEN - 1;
            Ks[r][d] = qkv[(size_t)kr * 3 * D_MODEL + D_MODEL + h0 + d];
            Vs[r][d] = qkv[(size_t)kr * 3 * D_MODEL + 2 * D_MODEL + h0 + d];
        }
        __syncthreads();

        float s;
        if (c0 + lane < nk) {
            float a0 = 0.f, a1 = 0.f, a2 = 0.f, a3 = 0.f;
            #pragma unroll
            for (int d = 0; d < DH; d += 4) {
                a0 = fmaf(Qs[q][d],     Ks[lane][d],     a0);
                a1 = fmaf(Qs[q][d + 1], Ks[lane][d + 1], a1);
                a2 = fmaf(Qs[q][d + 2], Ks[lane][d + 2], a2);
                a3 = fmaf(Qs[q][d + 3], Ks[lane][d + 3], a3);
            }
            s = (a0 + a1 + a2 + a3) * sc;
        } else {
            s = -1e30f;
        }
        float cm = s;
        #pragma unroll
        for (int off = 16; off; off >>= 1) cm = fmaxf(cm, __shfl_xor_sync(0xffffffff, cm, off));
        float mnew = fmaxf(m, cm);
        float p = __expf(s - mnew);
        if (c0 + lane >= nk) p = 0.f;
        float ps = p;
        #pragma unroll
        for (int off = 16; off; off >>= 1) ps += __shfl_xor_sync(0xffffffff, ps, off);
        float factor = __expf(m - mnew);
        l = l * factor + ps;
        m = mnew;
        o0 *= factor; o1 *= factor;
        #pragma unroll
        for (int k = 0; k < 32; k++) {
            float pk = __shfl_sync(0xffffffff, p, k);
            o0 = fmaf(pk, Vs[k][d0],     o0);
            o1 = fmaf(pk, Vs[k][d0 + 1], o1);
        }
        __syncthreads();
    }
    float invl = 1.f / l;
    float a = o0 * invl, b = o1 * invl;
    __nv_bfloat162 hi, lo;
    hi.x = __float2bfloat16(a);
    hi.y = __float2bfloat16(b);
    lo.x = __float2bfloat16(a - __bfloat162float(hi.x));
    lo.y = __float2bfloat16(b - __bfloat162float(hi.y));
    size_t rb = (size_t)(qrow0 + q) * 2 * D_MODEL;
    *(__nv_bfloat162*)(Oa + rb + h0 + d0)           = hi;
    *(__nv_bfloat162*)(Oa + rb + D_MODEL + h0 + d0) = lo;
}

// ---------------- host-side orchestration ----------------
extern "C" void kernel_launch(void* const* d_in, const int* in_sizes, int n_in,
                              void* d_out, int out_size) {
    const float* x       = (const float*)d_in[0];
    const float* cond    = (const float*)d_in[1];
    const float* qkv_w   = (const float*)d_in[2];
    const float* qkv_b   = (const float*)d_in[3];
    const float* out_w   = (const float*)d_in[4];
    const float* out_b   = (const float*)d_in[5];
    const float* mlp_w1  = (const float*)d_in[6];
    const float* mlp_b1  = (const float*)d_in[7];
    const float* mlp_w2  = (const float*)d_in[8];
    const float* mlp_b2  = (const float*)d_in[9];
    const float* ada1_w  = (const float*)d_in[10];
    const float* ada1_b  = (const float*)d_in[11];
    const float* gate1_w = (const float*)d_in[12];
    const float* gate1_b = (const float*)d_in[13];
    const float* ada2_w  = (const float*)d_in[14];
    const float* ada2_b  = (const float*)d_in[15];
    const float* gate2_w = (const float*)d_in[16];
    const float* gate2_b = (const float*)d_in[17];
    float* X = (float*)d_out;

    float *qkv_ptr, *mod_ptr, *rc_ptr, *rs_ptr;
    __nv_bfloat16 *abuf, *abuf2, *wbuf;
    cudaGetSymbolAddress((void**)&qkv_ptr, g_qkv);
    cudaGetSymbolAddress((void**)&mod_ptr, g_mod);
    cudaGetSymbolAddress((void**)&rc_ptr,  g_ropec);
    cudaGetSymbolAddress((void**)&rs_ptr,  g_ropes);
    cudaGetSymbolAddress((void**)&abuf,    g_abuf);
    cudaGetSymbolAddress((void**)&abuf2,   g_abuf2);
    cudaGetSymbolAddress((void**)&wbuf,    g_wbuf);

    const int SM128 = (2 * 128 * 80 + 2 * 32 * 272) * 3;  // 113664
    const int SM64  = (2 * 64 * 80 + 2 * 32 * 272) * 4;   // 110592 (4 stages)
    cudaFuncSetAttribute(mma_gemm<0, 128>, cudaFuncAttributeMaxDynamicSharedMemorySize, SM128);
    cudaFuncSetAttribute(mma_gemm<1, 128>, cudaFuncAttributeMaxDynamicSharedMemorySize, SM128);
    cudaFuncSetAttribute(mma_gemm<2, 64>,  cudaFuncAttributeMaxDynamicSharedMemorySize, SM64);

    cudaMemcpyAsync(X, x, (size_t)S_LEN * D_MODEL * sizeof(float), cudaMemcpyDeviceToDevice);

    rope_table_kernel<<<S_LEN * 32 / 256, 256>>>(rc_ptr, rs_ptr);

    modgate_kernel<<<L_LAYERS * 6 * D_MODEL / 256, 256>>>(
        cond, ada1_w, ada1_b, gate1_w, gate1_b, ada2_w, ada2_b, gate2_w, gate2_b, mod_ptr);

    for (int i = 0; i < L_LAYERS; i++) {
        const float* mod = mod_ptr + i * 6 * D_MODEL;
        int window = (i % 4 == 0) ? 128 : 8;

        // ---- attention block ----
        ln_mod_kernel<<<S_LEN, 256>>>(X, mod, mod + D_MODEL, abuf);

        split_w_kernel<<<dim3(3 * D_MODEL / 1024, D_MODEL), 256>>>(
            qkv_w + (size_t)i * D_MODEL * 3 * D_MODEL, wbuf, D_MODEL, 3 * D_MODEL);
        mma_gemm<0, 128><<<dim3(3 * D_MODEL / 128, S_LEN / 128), 256, SM128>>>(
            abuf, wbuf, qkv_b + i * 3 * D_MODEL, nullptr, qkv_ptr, nullptr, nullptr,
            S_LEN, 3 * D_MODEL, D_MODEL);

        rmsrope_kernel<<<dim3(S_LEN, 4), 256>>>(qkv_ptr, rc_ptr, rs_ptr);
        attn_kernel<<<dim3(NFRAMES, NH), 256>>>(qkv_ptr, abuf, window);

        split_w_kernel<<<dim3(D_MODEL / 1024, D_MODEL), 256>>>(
            out_w + (size_t)i * D_MODEL * D_MODEL, wbuf, D_MODEL, D_MODEL);
        mma_gemm<2, 64><<<dim3(D_MODEL / 128, S_LEN / 64), 256, SM64>>>(
            abuf, wbuf, out_b + i * D_MODEL, mod + 2 * D_MODEL, X, nullptr, X,
            S_LEN, D_MODEL, D_MODEL);

        // ---- MLP block ----
        ln_mod_kernel<<<S_LEN, 256>>>(X, mod + 3 * D_MODEL, mod + 4 * D_MODEL, abuf);

        split_w_kernel<<<dim3(DFF / 1024, D_MODEL), 256>>>(
            mlp_w1 + (size_t)i * D_MODEL * DFF, wbuf, D_MODEL, DFF);
        mma_gemm<1, 128><<<dim3(DFF / 128, S_LEN / 128), 256, SM128>>>(
            abuf, wbuf, mlp_b1 + i * DFF, nullptr, nullptr, abuf2, nullptr,
            S_LEN, DFF, D_MODEL);

        split_w_kernel<<<dim3(D_MODEL / 1024, DFF), 256>>>(
            mlp_w2 + (size_t)i * DFF * D_MODEL, wbuf, DFF, D_MODEL);
        mma_gemm<2, 64><<<dim3(D_MODEL / 128, S_LEN / 64), 256, SM64>>>(
            abuf2, wbuf, mlp_b2 + i * D_MODEL, mod + 5 * D_MODEL, X, nullptr, X,
            S_LEN, D_MODEL, DFF);
    }
}